// round 5
// baseline (speedup 1.0000x reference)
#include <cuda_runtime.h>
#include <cuda_bf16.h>
#include <math_constants.h>
#include <cstdint>

// Problem constants: B=16,T=2048,D=256,K=4096
#define N_TOK 32768
#define DIM   256
#define KCB   4096

#define TOK_TILE  128              // tokens per CTA (coarse)
#define CODE_TILE 64               // codes per E tile
#define N_CTILE   (KCB / CODE_TILE)  // 64
#define MARGIN    2.0e-3f
#define MAX_CAND  64

// ---------------- device scratch (no allocations allowed) -------------------
__device__ float  g_S[N_TOK];
__device__ float  g_c[KCB];
__device__ int    g_idx[N_TOK];
__device__ float  g_loss[N_TOK];
__device__ double g_part[128];
__device__ __align__(16) __nv_bfloat16 g_Xb[N_TOK * DIM];  // 16MB
__device__ __align__(16) __nv_bfloat16 g_Eb[KCB * DIM];    // 2MB
__device__ unsigned short g_cand[N_TOK][MAX_CAND];         // 4MB
__device__ int    g_ncand[N_TOK];

// ---------------- helpers ----------------------------------------------------
__device__ __forceinline__ uint32_t smem_to_u32(const void* p) {
    uint32_t a;
    asm("{ .reg .u64 t; cvta.to.shared.u64 t, %1; cvt.u32.u64 %0, t; }" : "=r"(a) : "l"(p));
    return a;
}
__device__ __forceinline__ void ldsm_x4(uint32_t* r, uint32_t addr) {
    asm volatile("ldmatrix.sync.aligned.m8n8.x4.shared.b16 {%0,%1,%2,%3}, [%4];"
        : "=r"(r[0]), "=r"(r[1]), "=r"(r[2]), "=r"(r[3]) : "r"(addr));
}
__device__ __forceinline__ void mma_bf16(float* c, const uint32_t* a, const uint32_t* b) {
    asm volatile("mma.sync.aligned.m16n8k16.row.col.f32.bf16.bf16.f32 "
        "{%0,%1,%2,%3}, {%4,%5,%6,%7}, {%8,%9}, {%0,%1,%2,%3};"
        : "+f"(c[0]), "+f"(c[1]), "+f"(c[2]), "+f"(c[3])
        : "r"(a[0]), "r"(a[1]), "r"(a[2]), "r"(a[3]), "r"(b[0]), "r"(b[1]));
}

// smem layout for coarse kernel (dynamic):
//   [0, 16384)          c table (4096 f32)
//   [16384, 81920)      X tile: 128 rows x 32 chunks(16B), chunk ^= row&7
//   [81920, 147456)     E tiles x2: each 64 rows x 32 chunks, same swizzle
#define SM_C 0
#define SM_X 16384
#define SM_E 81920
#define SMEM_TOTAL 147456

__device__ __forceinline__ uint32_t xaddr(uint32_t sb, int row, int ch) {
    return sb + SM_X + row * 512 + (((uint32_t)(ch ^ (row & 7))) << 4);
}
__device__ __forceinline__ uint32_t eaddr(uint32_t sb, int buf, int row, int ch) {
    return sb + SM_E + buf * 32768 + row * 512 + (((uint32_t)(ch ^ (row & 7))) << 4);
}

// ---------------------------------------------------------------------------
// Kernel 1: per-row sums of squares (exact fp32 sequential chain, bit-matching
// R2) + bf16 conversion of X and E + zero the candidate counters.
// ---------------------------------------------------------------------------
__global__ void prep_kernel(const float* __restrict__ X, const float* __restrict__ E) {
    int i = blockIdx.x * blockDim.x + threadIdx.x;
    if (i < N_TOK) {
        g_ncand[i] = 0;
        const float4* row = reinterpret_cast<const float4*>(X + (size_t)i * DIM);
        uint4* dst = reinterpret_cast<uint4*>(g_Xb + (size_t)i * DIM);
        float s = 0.0f;
        #pragma unroll 4
        for (int j = 0; j < DIM / 4; j += 2) {
            float4 a = row[j], b = row[j + 1];
            s = __fadd_rn(s, __fmul_rn(a.x, a.x)); s = __fadd_rn(s, __fmul_rn(a.y, a.y));
            s = __fadd_rn(s, __fmul_rn(a.z, a.z)); s = __fadd_rn(s, __fmul_rn(a.w, a.w));
            s = __fadd_rn(s, __fmul_rn(b.x, b.x)); s = __fadd_rn(s, __fmul_rn(b.y, b.y));
            s = __fadd_rn(s, __fmul_rn(b.z, b.z)); s = __fadd_rn(s, __fmul_rn(b.w, b.w));
            uint4 o;
            __nv_bfloat162 p0 = __floats2bfloat162_rn(a.x, a.y);
            __nv_bfloat162 p1 = __floats2bfloat162_rn(a.z, a.w);
            __nv_bfloat162 p2 = __floats2bfloat162_rn(b.x, b.y);
            __nv_bfloat162 p3 = __floats2bfloat162_rn(b.z, b.w);
            o.x = *reinterpret_cast<uint32_t*>(&p0);
            o.y = *reinterpret_cast<uint32_t*>(&p1);
            o.z = *reinterpret_cast<uint32_t*>(&p2);
            o.w = *reinterpret_cast<uint32_t*>(&p3);
            dst[j >> 1] = o;
        }
        g_S[i] = s;
    }
    if (i < KCB) {
        const float4* row = reinterpret_cast<const float4*>(E + (size_t)i * DIM);
        uint4* dst = reinterpret_cast<uint4*>(g_Eb + (size_t)i * DIM);
        float s = 0.0f;
        #pragma unroll 4
        for (int j = 0; j < DIM / 4; j += 2) {
            float4 a = row[j], b = row[j + 1];
            s = __fadd_rn(s, __fmul_rn(a.x, a.x)); s = __fadd_rn(s, __fmul_rn(a.y, a.y));
            s = __fadd_rn(s, __fmul_rn(a.z, a.z)); s = __fadd_rn(s, __fmul_rn(a.w, a.w));
            s = __fadd_rn(s, __fmul_rn(b.x, b.x)); s = __fadd_rn(s, __fmul_rn(b.y, b.y));
            s = __fadd_rn(s, __fmul_rn(b.z, b.z)); s = __fadd_rn(s, __fmul_rn(b.w, b.w));
            uint4 o;
            __nv_bfloat162 p0 = __floats2bfloat162_rn(a.x, a.y);
            __nv_bfloat162 p1 = __floats2bfloat162_rn(a.z, a.w);
            __nv_bfloat162 p2 = __floats2bfloat162_rn(b.x, b.y);
            __nv_bfloat162 p3 = __floats2bfloat162_rn(b.z, b.w);
            o.x = *reinterpret_cast<uint32_t*>(&p0);
            o.y = *reinterpret_cast<uint32_t*>(&p1);
            o.z = *reinterpret_cast<uint32_t*>(&p2);
            o.w = *reinterpret_cast<uint32_t*>(&p3);
            dst[j >> 1] = o;
        }
        g_c[i] = s;
    }
}

// ---------------------------------------------------------------------------
// Kernel 2: coarse bf16 HMMA scoring + margin candidate collection.
// CTA: 128 tokens x 4096 codes, K=256 resident in smem.
// 8 warps as 4(M) x 2(N); warp tile 32 tokens x 32 codes per E tile.
// coarse score s_hat = fmaf(-2, m_bf16, c); collect s_hat <= runmin + MARGIN.
// ---------------------------------------------------------------------------
__global__ __launch_bounds__(256) void coarse_kernel() {
    extern __shared__ __align__(1024) char smem[];
    const int tid = threadIdx.x, wid = tid >> 5, lane = tid & 31;
    const int gid = lane >> 2, tig = lane & 3;
    const int wm = wid >> 1, wn = wid & 1;
    const int mb = blockIdx.x * TOK_TILE;
    uint32_t sb = smem_to_u32(smem);
    float* cbuf = reinterpret_cast<float*>(smem + SM_C);

    // c table
    #pragma unroll
    for (int i = 0; i < KCB / 256; i++) cbuf[tid + i * 256] = g_c[tid + i * 256];

    // X tile: 128 rows x 32 chunks
    #pragma unroll
    for (int i = 0; i < 16; i++) {
        int v = tid + i * 256;
        int row = v >> 5, ch = v & 31;
        uint4 d = *reinterpret_cast<const uint4*>(g_Xb + (size_t)(mb + row) * DIM + ch * 8);
        *reinterpret_cast<uint4*>(smem + SM_X + row * 512 + ((uint32_t)(ch ^ (row & 7)) << 4)) = d;
    }

    // E tile 0 into buffer 0
    #pragma unroll
    for (int i = 0; i < 8; i++) {
        int v = tid + i * 256;
        int row = v >> 5, ch = v & 31;
        uint4 d = *reinterpret_cast<const uint4*>(g_Eb + (size_t)row * DIM + ch * 8);
        *reinterpret_cast<uint4*>(smem + SM_E + row * 512 + ((uint32_t)(ch ^ (row & 7)) << 4)) = d;
    }

    float runmin[4] = {CUDART_INF_F, CUDART_INF_F, CUDART_INF_F, CUDART_INF_F};

    // A ldmatrix lane coords (fixed per thread): row = wm*32 + mi*16 + (lane&15),
    // chunk = kc + (lane>>4)
    const int a_r = (lane & 15);
    const int a_c = (lane >> 4);
    // B ldmatrix lane coords: row = wn*32 + np*16 + (lane&7) + ((lane>>4)<<3),
    // chunk = kc + ((lane>>3)&1)
    const int b_r = (lane & 7) + ((lane >> 4) << 3);
    const int b_c = ((lane >> 3) & 1);

    for (int ct = 0; ct < N_CTILE; ct++) {
        __syncthreads();   // buf (ct&1) stores visible; buf (ct^1) reads retired
        const int cur = ct & 1;

        uint4 nreg[8];
        if (ct < N_CTILE - 1) {
            #pragma unroll
            for (int i = 0; i < 8; i++) {
                int v = tid + i * 256;
                int row = v >> 5, ch = v & 31;
                nreg[i] = *reinterpret_cast<const uint4*>(
                    g_Eb + (size_t)((ct + 1) * CODE_TILE + row) * DIM + ch * 8);
            }
        }

        float acc[2][4][4];
        #pragma unroll
        for (int mi = 0; mi < 2; mi++)
            #pragma unroll
            for (int ni = 0; ni < 4; ni++)
                #pragma unroll
                for (int e = 0; e < 4; e++) acc[mi][ni][e] = 0.0f;

        #pragma unroll
        for (int ks = 0; ks < 16; ks++) {
            const int kc = ks * 2;
            uint32_t a[2][4], b[2][4];
            #pragma unroll
            for (int mi = 0; mi < 2; mi++) {
                int r = wm * 32 + mi * 16 + a_r;
                ldsm_x4(a[mi], xaddr(sb, r, kc + a_c));
            }
            #pragma unroll
            for (int np = 0; np < 2; np++) {
                int r = wn * 32 + np * 16 + b_r;
                ldsm_x4(b[np], eaddr(sb, cur, r, kc + b_c));
            }
            #pragma unroll
            for (int mi = 0; mi < 2; mi++)
                #pragma unroll
                for (int ni = 0; ni < 4; ni++)
                    mma_bf16(acc[mi][ni], a[mi], &b[ni >> 1][(ni & 1) * 2]);
        }

        // epilogue: s_hat, running min, candidate append
        #pragma unroll
        for (int mi = 0; mi < 2; mi++) {
            #pragma unroll
            for (int h = 0; h < 2; h++) {
                const int slot = mi * 2 + h;
                const int token = mb + wm * 32 + mi * 16 + gid + h * 8;
                float s[8];
                float tmin = CUDART_INF_F;
                #pragma unroll
                for (int ni = 0; ni < 4; ni++) {
                    int code = ct * CODE_TILE + wn * 32 + ni * 8 + tig * 2;
                    s[ni * 2 + 0] = fmaf(-2.0f, acc[mi][ni][h * 2 + 0], cbuf[code]);
                    s[ni * 2 + 1] = fmaf(-2.0f, acc[mi][ni][h * 2 + 1], cbuf[code + 1]);
                    tmin = fminf(tmin, fminf(s[ni * 2], s[ni * 2 + 1]));
                }
                runmin[slot] = fminf(runmin[slot], tmin);
                const float th = runmin[slot] + MARGIN;
                if (tmin <= th) {
                    #pragma unroll
                    for (int ni = 0; ni < 4; ni++) {
                        #pragma unroll
                        for (int e = 0; e < 2; e++) {
                            if (s[ni * 2 + e] <= th) {
                                int code = ct * CODE_TILE + wn * 32 + ni * 8 + tig * 2 + e;
                                int p = atomicAdd(&g_ncand[token], 1);
                                if (p < MAX_CAND) g_cand[token][p] = (unsigned short)code;
                            }
                        }
                    }
                }
            }
        }

        // stage next tile into the other buffer
        if (ct < N_CTILE - 1) {
            #pragma unroll
            for (int i = 0; i < 8; i++) {
                int v = tid + i * 256;
                int row = v >> 5, ch = v & 31;
                *reinterpret_cast<uint4*>(smem + SM_E + (cur ^ 1) * 32768 + row * 512 +
                                          ((uint32_t)(ch ^ (row & 7)) << 4)) = nreg[i];
            }
        }
    }
}

// ---------------------------------------------------------------------------
// Kernel 3: exact fp32 rescore of candidates (bit-identical to R2 chain).
// One warp per token; lexicographic (d2, idx) min; overflow -> full exact scan.
// ---------------------------------------------------------------------------
__global__ void rescore_kernel(const float* __restrict__ X, const float* __restrict__ E,
                               float* __restrict__ out_idx_f) {
    int token = (blockIdx.x * blockDim.x + threadIdx.x) >> 5;
    int lane = threadIdx.x & 31;
    if (token >= N_TOK) return;
    int n = g_ncand[token];
    float S = g_S[token];
    const float4* xr = reinterpret_cast<const float4*>(X + (size_t)token * DIM);

    float bestv = CUDART_INF_F;
    int   besti = 0x7fffffff;

    if (n <= MAX_CAND) {
        for (int sidx = lane; sidx < n; sidx += 32) {
            int code = g_cand[token][sidx];
            const float4* er = reinterpret_cast<const float4*>(E + (size_t)code * DIM);
            float m = 0.0f;
            #pragma unroll 8
            for (int k = 0; k < DIM / 4; k++) {
                float4 x = xr[k], e = er[k];
                m = fmaf(x.x, e.x, m); m = fmaf(x.y, e.y, m);
                m = fmaf(x.z, e.z, m); m = fmaf(x.w, e.w, m);
            }
            float t = fmaf(-2.0f, m, S);
            float d2 = __fadd_rn(t, g_c[code]);
            if (d2 < bestv || (d2 == bestv && code < besti)) { bestv = d2; besti = code; }
        }
    } else {
        for (int code = lane; code < KCB; code += 32) {
            const float4* er = reinterpret_cast<const float4*>(E + (size_t)code * DIM);
            float m = 0.0f;
            #pragma unroll 8
            for (int k = 0; k < DIM / 4; k++) {
                float4 x = xr[k], e = er[k];
                m = fmaf(x.x, e.x, m); m = fmaf(x.y, e.y, m);
                m = fmaf(x.z, e.z, m); m = fmaf(x.w, e.w, m);
            }
            float t = fmaf(-2.0f, m, S);
            float d2 = __fadd_rn(t, g_c[code]);
            if (d2 < bestv || (d2 == bestv && code < besti)) { bestv = d2; besti = code; }
        }
    }
    #pragma unroll
    for (int off = 16; off >= 1; off >>= 1) {
        float ov = __shfl_xor_sync(0xffffffffu, bestv, off);
        int   oi = __shfl_xor_sync(0xffffffffu, besti, off);
        if (ov < bestv || (ov == bestv && oi < besti)) { bestv = ov; besti = oi; }
    }
    if (lane == 0) {
        g_idx[token] = besti;
        out_idx_f[token] = (float)besti;
    }
}

// ---------------------------------------------------------------------------
// Kernel 4: gather + straight-through output + per-token loss (R2, bit-exact).
// Quantized region is only 4B-aligned -> scalar stores.
// ---------------------------------------------------------------------------
__global__ void output_kernel(const float* __restrict__ X, const float* __restrict__ E,
                              float* __restrict__ out_q) {
    int warp = (blockIdx.x * blockDim.x + threadIdx.x) >> 5;
    int lane = threadIdx.x & 31;
    if (warp >= N_TOK) return;
    int code = g_idx[warp];
    const float4* xr = reinterpret_cast<const float4*>(X + (size_t)warp * DIM);
    const float4* er = reinterpret_cast<const float4*>(E + (size_t)code * DIM);
    float* qr = out_q + (size_t)warp * DIM;

    float ls = 0.0f;
    #pragma unroll
    for (int j = lane; j < DIM / 4; j += 32) {
        float4 x = xr[j], e = er[j];
        float4 d, o;
        d.x = __fadd_rn(e.x, -x.x); d.y = __fadd_rn(e.y, -x.y);
        d.z = __fadd_rn(e.z, -x.z); d.w = __fadd_rn(e.w, -x.w);
        ls = __fadd_rn(ls, __fmul_rn(d.x, d.x));
        ls = __fadd_rn(ls, __fmul_rn(d.y, d.y));
        ls = __fadd_rn(ls, __fmul_rn(d.z, d.z));
        ls = __fadd_rn(ls, __fmul_rn(d.w, d.w));
        o.x = __fadd_rn(x.x, d.x); o.y = __fadd_rn(x.y, d.y);
        o.z = __fadd_rn(x.z, d.z); o.w = __fadd_rn(x.w, d.w);
        qr[j * 4 + 0] = o.x;
        qr[j * 4 + 1] = o.y;
        qr[j * 4 + 2] = o.z;
        qr[j * 4 + 3] = o.w;
    }
    #pragma unroll
    for (int off = 16; off >= 1; off >>= 1)
        ls = __fadd_rn(ls, __shfl_xor_sync(0xffffffffu, ls, off));
    if (lane == 0) g_loss[warp] = ls;
}

// ---------------------------------------------------------------------------
// Kernels 5+6: two-stage deterministic double-precision loss reduction.
// ---------------------------------------------------------------------------
__global__ void finalize1_kernel() {
    __shared__ double sh[256];
    int b = blockIdx.x;
    sh[threadIdx.x] = (double)g_loss[b * 256 + threadIdx.x];
    __syncthreads();
    for (int off = 128; off >= 1; off >>= 1) {
        if (threadIdx.x < off) sh[threadIdx.x] += sh[threadIdx.x + off];
        __syncthreads();
    }
    if (threadIdx.x == 0) g_part[b] = sh[0];
}
__global__ void finalize2_kernel(float* __restrict__ out) {
    __shared__ double sh[128];
    sh[threadIdx.x] = g_part[threadIdx.x];
    __syncthreads();
    for (int off = 64; off >= 1; off >>= 1) {
        if (threadIdx.x < off) sh[threadIdx.x] += sh[threadIdx.x + off];
        __syncthreads();
    }
    if (threadIdx.x == 0)
        out[0] = (float)(0.5 * sh[0] / ((double)N_TOK * (double)DIM));
}

// ---------------------------------------------------------------------------
extern "C" void kernel_launch(void* const* d_in, const int* in_sizes, int n_in,
                              void* d_out, int out_size) {
    const float* X = (const float*)d_in[0];   // embedding_tokens [N, D]
    const float* E = (const float*)d_in[1];   // embeddings       [K, D]
    float* out = (float*)d_out;
    float* out_q   = out + 1;
    float* out_idx = out + 1 + (size_t)N_TOK * DIM;

    static int smem_set = 0;
    if (!smem_set) {
        cudaFuncSetAttribute(coarse_kernel, cudaFuncAttributeMaxDynamicSharedMemorySize, SMEM_TOTAL);
        smem_set = 1;
    }

    prep_kernel<<<N_TOK / 256, 256>>>(X, E);
    coarse_kernel<<<N_TOK / TOK_TILE, 256, SMEM_TOTAL>>>();
    rescore_kernel<<<(N_TOK * 32) / 256, 256>>>(X, E, out_idx);
    output_kernel<<<(N_TOK * 32) / 256, 256>>>(X, E, out_q);
    finalize1_kernel<<<128, 256>>>();
    finalize2_kernel<<<1, 128>>>(out);
}

// round 6
// speedup vs baseline: 19.5412x; 19.5412x over previous
#include <cuda_runtime.h>
#include <cuda_bf16.h>
#include <math_constants.h>
#include <cstdint>

// Problem constants: B=16,T=2048,D=256,K=4096
#define N_TOK 32768
#define DIM   256
#define KCB   4096

#define TOK_TILE  128                // tokens per CTA (coarse)
#define CODE_TILE 64                 // codes per E tile
#define N_CTILE   (KCB / CODE_TILE)  // 64
#define MARGIN    2.0e-3f
#define MAX_CAND  64

// ---------------- device scratch (no allocations allowed) -------------------
__device__ float  g_S[N_TOK];
__device__ float  g_c[KCB];
__device__ int    g_idx[N_TOK];
__device__ float  g_loss[N_TOK];
__device__ double g_part[128];
__device__ __align__(16) __nv_bfloat16 g_Xb[N_TOK * DIM];  // 16MB
__device__ __align__(16) __nv_bfloat16 g_Eb[KCB * DIM];    // 2MB
__device__ unsigned short g_cand[N_TOK][MAX_CAND];         // 4MB
__device__ int    g_ncand[N_TOK];

// ---------------- helpers ----------------------------------------------------
__device__ __forceinline__ uint32_t smem_to_u32(const void* p) {
    uint32_t a;
    asm("{ .reg .u64 t; cvta.to.shared.u64 t, %1; cvt.u32.u64 %0, t; }" : "=r"(a) : "l"(p));
    return a;
}
__device__ __forceinline__ void ldsm_x4(uint32_t* r, uint32_t addr) {
    asm volatile("ldmatrix.sync.aligned.m8n8.x4.shared.b16 {%0,%1,%2,%3}, [%4];"
        : "=r"(r[0]), "=r"(r[1]), "=r"(r[2]), "=r"(r[3]) : "r"(addr));
}
__device__ __forceinline__ void mma_bf16(float* c, const uint32_t* a, const uint32_t* b) {
    asm volatile("mma.sync.aligned.m16n8k16.row.col.f32.bf16.bf16.f32 "
        "{%0,%1,%2,%3}, {%4,%5,%6,%7}, {%8,%9}, {%0,%1,%2,%3};"
        : "+f"(c[0]), "+f"(c[1]), "+f"(c[2]), "+f"(c[3])
        : "r"(a[0]), "r"(a[1]), "r"(a[2]), "r"(a[3]), "r"(b[0]), "r"(b[1]));
}
__device__ __forceinline__ void cp_async16(uint32_t dst_smem, const void* src) {
    asm volatile("cp.async.cg.shared.global [%0], [%1], 16;" :: "r"(dst_smem), "l"(src) : "memory");
}
__device__ __forceinline__ void cp_commit() { asm volatile("cp.async.commit_group;" ::: "memory"); }
__device__ __forceinline__ void cp_wait0()  { asm volatile("cp.async.wait_group 0;"  ::: "memory"); }

// order-preserving float<->uint encoding (for atomicMin on float values)
__device__ __forceinline__ uint32_t fenc(float f) {
    uint32_t u = __float_as_uint(f);
    return (u & 0x80000000u) ? ~u : (u | 0x80000000u);
}
__device__ __forceinline__ float fdec(uint32_t u) {
    uint32_t b = (u & 0x80000000u) ? (u & 0x7FFFFFFFu) : ~u;
    return __uint_as_float(b);
}

// smem layout for coarse kernel (dynamic):
//   [0, 16384)          c table (4096 f32)
//   [16384, 81920)      X tile: 128 rows x 32 chunks(16B), chunk ^= row&7
//   [81920, 147456)     E tiles x2: each 64 rows x 32 chunks, same swizzle
//   [147456, 147968)    per-token coarse running min (128 x u32, flip-encoded)
#define SM_C 0
#define SM_X 16384
#define SM_E 81920
#define SM_MIN 147456
#define SMEM_TOTAL 147968

// ---------------------------------------------------------------------------
// Kernel 1: per-row sums of squares (exact fp32 sequential chain, bit-matching
// R2) + bf16 conversion of X and E + zero the candidate counters.
// ---------------------------------------------------------------------------
__global__ void prep_kernel(const float* __restrict__ X, const float* __restrict__ E) {
    int i = blockIdx.x * blockDim.x + threadIdx.x;
    if (i < N_TOK) {
        g_ncand[i] = 0;
        const float4* row = reinterpret_cast<const float4*>(X + (size_t)i * DIM);
        uint4* dst = reinterpret_cast<uint4*>(g_Xb + (size_t)i * DIM);
        float s = 0.0f;
        #pragma unroll 4
        for (int j = 0; j < DIM / 4; j += 2) {
            float4 a = row[j], b = row[j + 1];
            s = __fadd_rn(s, __fmul_rn(a.x, a.x)); s = __fadd_rn(s, __fmul_rn(a.y, a.y));
            s = __fadd_rn(s, __fmul_rn(a.z, a.z)); s = __fadd_rn(s, __fmul_rn(a.w, a.w));
            s = __fadd_rn(s, __fmul_rn(b.x, b.x)); s = __fadd_rn(s, __fmul_rn(b.y, b.y));
            s = __fadd_rn(s, __fmul_rn(b.z, b.z)); s = __fadd_rn(s, __fmul_rn(b.w, b.w));
            uint4 o;
            __nv_bfloat162 p0 = __floats2bfloat162_rn(a.x, a.y);
            __nv_bfloat162 p1 = __floats2bfloat162_rn(a.z, a.w);
            __nv_bfloat162 p2 = __floats2bfloat162_rn(b.x, b.y);
            __nv_bfloat162 p3 = __floats2bfloat162_rn(b.z, b.w);
            o.x = *reinterpret_cast<uint32_t*>(&p0);
            o.y = *reinterpret_cast<uint32_t*>(&p1);
            o.z = *reinterpret_cast<uint32_t*>(&p2);
            o.w = *reinterpret_cast<uint32_t*>(&p3);
            dst[j >> 1] = o;
        }
        g_S[i] = s;
    }
    if (i < KCB) {
        const float4* row = reinterpret_cast<const float4*>(E + (size_t)i * DIM);
        uint4* dst = reinterpret_cast<uint4*>(g_Eb + (size_t)i * DIM);
        float s = 0.0f;
        #pragma unroll 4
        for (int j = 0; j < DIM / 4; j += 2) {
            float4 a = row[j], b = row[j + 1];
            s = __fadd_rn(s, __fmul_rn(a.x, a.x)); s = __fadd_rn(s, __fmul_rn(a.y, a.y));
            s = __fadd_rn(s, __fmul_rn(a.z, a.z)); s = __fadd_rn(s, __fmul_rn(a.w, a.w));
            s = __fadd_rn(s, __fmul_rn(b.x, b.x)); s = __fadd_rn(s, __fmul_rn(b.y, b.y));
            s = __fadd_rn(s, __fmul_rn(b.z, b.z)); s = __fadd_rn(s, __fmul_rn(b.w, b.w));
            uint4 o;
            __nv_bfloat162 p0 = __floats2bfloat162_rn(a.x, a.y);
            __nv_bfloat162 p1 = __floats2bfloat162_rn(a.z, a.w);
            __nv_bfloat162 p2 = __floats2bfloat162_rn(b.x, b.y);
            __nv_bfloat162 p3 = __floats2bfloat162_rn(b.z, b.w);
            o.x = *reinterpret_cast<uint32_t*>(&p0);
            o.y = *reinterpret_cast<uint32_t*>(&p1);
            o.z = *reinterpret_cast<uint32_t*>(&p2);
            o.w = *reinterpret_cast<uint32_t*>(&p3);
            dst[j >> 1] = o;
        }
        g_c[i] = s;
    }
}

// ---------------------------------------------------------------------------
// Kernel 2: coarse bf16 HMMA scoring + margin candidate collection.
// CTA: 128 tokens x 4096 codes, K=256 resident in smem.
// 8 warps as 4(M) x 2(N); warp tile 32 tokens x 32 codes per E tile.
// s_hat = fmaf(-2, m_bf16, c). Token-GLOBAL running min kept in smem via
// atomicMin on flip-encoded floats; collect s_hat <= tokenmin + MARGIN.
// E tiles double-buffered via cp.async (overlaps loads with MMA).
// ---------------------------------------------------------------------------
__global__ __launch_bounds__(256) void coarse_kernel() {
    extern __shared__ __align__(1024) char smem[];
    const int tid = threadIdx.x, wid = tid >> 5, lane = tid & 31;
    const int gid = lane >> 2, tig = lane & 3;
    const int wm = wid >> 1, wn = wid & 1;
    const int mb = blockIdx.x * TOK_TILE;
    uint32_t sb = smem_to_u32(smem);
    float* cbuf = reinterpret_cast<float*>(smem + SM_C);
    uint32_t* smin = reinterpret_cast<uint32_t*>(smem + SM_MIN);

    // init per-token coarse min to +inf (encoded)
    if (tid < TOK_TILE) smin[tid] = 0xFF800000u;  // fenc(+inf)

    // c table
    #pragma unroll
    for (int i = 0; i < KCB / 256; i++) cbuf[tid + i * 256] = g_c[tid + i * 256];

    // X tile: 128 rows x 32 chunks (plain stores)
    #pragma unroll
    for (int i = 0; i < 16; i++) {
        int v = tid + i * 256;
        int row = v >> 5, ch = v & 31;
        uint4 d = *reinterpret_cast<const uint4*>(g_Xb + (size_t)(mb + row) * DIM + ch * 8);
        *reinterpret_cast<uint4*>(smem + SM_X + row * 512 + ((uint32_t)(ch ^ (row & 7)) << 4)) = d;
    }

    // E tile 0 into buffer 0 via cp.async
    #pragma unroll
    for (int i = 0; i < 8; i++) {
        int v = tid + i * 256;
        int row = v >> 5, ch = v & 31;
        cp_async16(sb + SM_E + row * 512 + ((uint32_t)(ch ^ (row & 7)) << 4),
                   g_Eb + (size_t)row * DIM + ch * 8);
    }
    cp_commit();
    cp_wait0();
    __syncthreads();

    // ldmatrix lane coords
    const int a_r = (lane & 15);
    const int a_c = (lane >> 4);
    const int b_r = (lane & 7) + ((lane >> 4) << 3);
    const int b_c = ((lane >> 3) & 1);

    for (int ct = 0; ct < N_CTILE; ct++) {
        const int cur = ct & 1;

        // stage next E tile into the other buffer (async, overlapped with MMA)
        if (ct < N_CTILE - 1) {
            #pragma unroll
            for (int i = 0; i < 8; i++) {
                int v = tid + i * 256;
                int row = v >> 5, ch = v & 31;
                cp_async16(sb + SM_E + (cur ^ 1) * 32768 + row * 512 +
                               ((uint32_t)(ch ^ (row & 7)) << 4),
                           g_Eb + (size_t)((ct + 1) * CODE_TILE + row) * DIM + ch * 8);
            }
            cp_commit();
        }

        float acc[2][4][4];
        #pragma unroll
        for (int mi = 0; mi < 2; mi++)
            #pragma unroll
            for (int ni = 0; ni < 4; ni++)
                #pragma unroll
                for (int e = 0; e < 4; e++) acc[mi][ni][e] = 0.0f;

        #pragma unroll
        for (int ks = 0; ks < 16; ks++) {
            const int kc = ks * 2;
            uint32_t a[2][4], b[2][4];
            #pragma unroll
            for (int mi = 0; mi < 2; mi++) {
                int r = wm * 32 + mi * 16 + a_r;
                ldsm_x4(a[mi], sb + SM_X + r * 512 + ((uint32_t)((kc + a_c) ^ (r & 7)) << 4));
            }
            #pragma unroll
            for (int np = 0; np < 2; np++) {
                int r = wn * 32 + np * 16 + b_r;
                ldsm_x4(b[np], sb + SM_E + cur * 32768 + r * 512 +
                               ((uint32_t)((kc + b_c) ^ (r & 7)) << 4));
            }
            #pragma unroll
            for (int mi = 0; mi < 2; mi++)
                #pragma unroll
                for (int ni = 0; ni < 4; ni++)
                    mma_bf16(acc[mi][ni], a[mi], &b[ni >> 1][(ni & 1) * 2]);
        }

        // epilogue: s_hat, token-global running min, candidate append
        #pragma unroll
        for (int mi = 0; mi < 2; mi++) {
            #pragma unroll
            for (int h = 0; h < 2; h++) {
                const int tl = wm * 32 + mi * 16 + gid + h * 8;  // token-local
                const int token = mb + tl;
                float s[8];
                float tmin = CUDART_INF_F;
                #pragma unroll
                for (int ni = 0; ni < 4; ni++) {
                    int code = ct * CODE_TILE + wn * 32 + ni * 8 + tig * 2;
                    s[ni * 2 + 0] = fmaf(-2.0f, acc[mi][ni][h * 2 + 0], cbuf[code]);
                    s[ni * 2 + 1] = fmaf(-2.0f, acc[mi][ni][h * 2 + 1], cbuf[code + 1]);
                    tmin = fminf(tmin, fminf(s[ni * 2], s[ni * 2 + 1]));
                }
                float curf = fdec(smin[tl]);          // stale-larger read is safe
                if (tmin < curf) atomicMin(&smin[tl], fenc(tmin));
                const float th = fminf(curf, tmin) + MARGIN;
                if (tmin <= th) {
                    #pragma unroll
                    for (int ni = 0; ni < 4; ni++) {
                        #pragma unroll
                        for (int e = 0; e < 2; e++) {
                            if (s[ni * 2 + e] <= th) {
                                int code = ct * CODE_TILE + wn * 32 + ni * 8 + tig * 2 + e;
                                int p = atomicAdd(&g_ncand[token], 1);
                                if (p < MAX_CAND) g_cand[token][p] = (unsigned short)code;
                            }
                        }
                    }
                }
            }
        }

        if (ct < N_CTILE - 1) cp_wait0();
        __syncthreads();
    }
}

// ---------------------------------------------------------------------------
// Kernel 3: exact fp32 rescore of candidates (bit-identical to R2 chain).
// One warp per token; lexicographic (d2, idx) min; overflow -> full exact scan.
// ---------------------------------------------------------------------------
__global__ void rescore_kernel(const float* __restrict__ X, const float* __restrict__ E,
                               float* __restrict__ out_idx_f) {
    int token = (blockIdx.x * blockDim.x + threadIdx.x) >> 5;
    int lane = threadIdx.x & 31;
    if (token >= N_TOK) return;
    int n = g_ncand[token];
    float S = g_S[token];
    const float4* xr = reinterpret_cast<const float4*>(X + (size_t)token * DIM);

    float bestv = CUDART_INF_F;
    int   besti = 0x7fffffff;

    if (n <= MAX_CAND) {
        for (int sidx = lane; sidx < n; sidx += 32) {
            int code = g_cand[token][sidx];
            const float4* er = reinterpret_cast<const float4*>(E + (size_t)code * DIM);
            float m = 0.0f;
            #pragma unroll 8
            for (int k = 0; k < DIM / 4; k++) {
                float4 x = xr[k], e = er[k];
                m = fmaf(x.x, e.x, m); m = fmaf(x.y, e.y, m);
                m = fmaf(x.z, e.z, m); m = fmaf(x.w, e.w, m);
            }
            float t = fmaf(-2.0f, m, S);
            float d2 = __fadd_rn(t, g_c[code]);
            if (d2 < bestv || (d2 == bestv && code < besti)) { bestv = d2; besti = code; }
        }
    } else {
        for (int code = lane; code < KCB; code += 32) {
            const float4* er = reinterpret_cast<const float4*>(E + (size_t)code * DIM);
            float m = 0.0f;
            #pragma unroll 8
            for (int k = 0; k < DIM / 4; k++) {
                float4 x = xr[k], e = er[k];
                m = fmaf(x.x, e.x, m); m = fmaf(x.y, e.y, m);
                m = fmaf(x.z, e.z, m); m = fmaf(x.w, e.w, m);
            }
            float t = fmaf(-2.0f, m, S);
            float d2 = __fadd_rn(t, g_c[code]);
            if (d2 < bestv || (d2 == bestv && code < besti)) { bestv = d2; besti = code; }
        }
    }
    #pragma unroll
    for (int off = 16; off >= 1; off >>= 1) {
        float ov = __shfl_xor_sync(0xffffffffu, bestv, off);
        int   oi = __shfl_xor_sync(0xffffffffu, besti, off);
        if (ov < bestv || (ov == bestv && oi < besti)) { bestv = ov; besti = oi; }
    }
    if (lane == 0) {
        g_idx[token] = besti;
        out_idx_f[token] = (float)besti;
    }
}

// ---------------------------------------------------------------------------
// Kernel 4: gather + straight-through output + per-token loss (R2, bit-exact).
// Quantized region is only 4B-aligned -> scalar stores.
// ---------------------------------------------------------------------------
__global__ void output_kernel(const float* __restrict__ X, const float* __restrict__ E,
                              float* __restrict__ out_q) {
    int warp = (blockIdx.x * blockDim.x + threadIdx.x) >> 5;
    int lane = threadIdx.x & 31;
    if (warp >= N_TOK) return;
    int code = g_idx[warp];
    const float4* xr = reinterpret_cast<const float4*>(X + (size_t)warp * DIM);
    const float4* er = reinterpret_cast<const float4*>(E + (size_t)code * DIM);
    float* qr = out_q + (size_t)warp * DIM;

    float ls = 0.0f;
    #pragma unroll
    for (int j = lane; j < DIM / 4; j += 32) {
        float4 x = xr[j], e = er[j];
        float4 d, o;
        d.x = __fadd_rn(e.x, -x.x); d.y = __fadd_rn(e.y, -x.y);
        d.z = __fadd_rn(e.z, -x.z); d.w = __fadd_rn(e.w, -x.w);
        ls = __fadd_rn(ls, __fmul_rn(d.x, d.x));
        ls = __fadd_rn(ls, __fmul_rn(d.y, d.y));
        ls = __fadd_rn(ls, __fmul_rn(d.z, d.z));
        ls = __fadd_rn(ls, __fmul_rn(d.w, d.w));
        o.x = __fadd_rn(x.x, d.x); o.y = __fadd_rn(x.y, d.y);
        o.z = __fadd_rn(x.z, d.z); o.w = __fadd_rn(x.w, d.w);
        qr[j * 4 + 0] = o.x;
        qr[j * 4 + 1] = o.y;
        qr[j * 4 + 2] = o.z;
        qr[j * 4 + 3] = o.w;
    }
    #pragma unroll
    for (int off = 16; off >= 1; off >>= 1)
        ls = __fadd_rn(ls, __shfl_xor_sync(0xffffffffu, ls, off));
    if (lane == 0) g_loss[warp] = ls;
}

// ---------------------------------------------------------------------------
// Kernels 5+6: two-stage deterministic double-precision loss reduction.
// ---------------------------------------------------------------------------
__global__ void finalize1_kernel() {
    __shared__ double sh[256];
    int b = blockIdx.x;
    sh[threadIdx.x] = (double)g_loss[b * 256 + threadIdx.x];
    __syncthreads();
    for (int off = 128; off >= 1; off >>= 1) {
        if (threadIdx.x < off) sh[threadIdx.x] += sh[threadIdx.x + off];
        __syncthreads();
    }
    if (threadIdx.x == 0) g_part[b] = sh[0];
}
__global__ void finalize2_kernel(float* __restrict__ out) {
    __shared__ double sh[128];
    sh[threadIdx.x] = g_part[threadIdx.x];
    __syncthreads();
    for (int off = 64; off >= 1; off >>= 1) {
        if (threadIdx.x < off) sh[threadIdx.x] += sh[threadIdx.x + off];
        __syncthreads();
    }
    if (threadIdx.x == 0)
        out[0] = (float)(0.5 * sh[0] / ((double)N_TOK * (double)DIM));
}

// ---------------------------------------------------------------------------
extern "C" void kernel_launch(void* const* d_in, const int* in_sizes, int n_in,
                              void* d_out, int out_size) {
    const float* X = (const float*)d_in[0];   // embedding_tokens [N, D]
    const float* E = (const float*)d_in[1];   // embeddings       [K, D]
    float* out = (float*)d_out;
    float* out_q   = out + 1;
    float* out_idx = out + 1 + (size_t)N_TOK * DIM;

    static int smem_set = 0;
    if (!smem_set) {
        cudaFuncSetAttribute(coarse_kernel, cudaFuncAttributeMaxDynamicSharedMemorySize, SMEM_TOTAL);
        smem_set = 1;
    }

    prep_kernel<<<N_TOK / 256, 256>>>(X, E);
    coarse_kernel<<<N_TOK / TOK_TILE, 256, SMEM_TOTAL>>>();
    rescore_kernel<<<(N_TOK * 32) / 256, 256>>>(X, E, out_idx);
    output_kernel<<<(N_TOK * 32) / 256, 256>>>(X, E, out_q);
    finalize1_kernel<<<128, 256>>>();
    finalize2_kernel<<<1, 128>>>(out);
}

// round 7
// speedup vs baseline: 20.5302x; 1.0506x over previous
#include <cuda_runtime.h>
#include <math_constants.h>
#include <cstdint>

// Problem constants: B=16,T=2048,D=256,K=4096
#define N_TOK 32768
#define DIM   256
#define KCB   4096
#define NKCH  (DIM / 4)     // 64 packed int32 k-chunks per row

#define TOK_TILE  128
#define CODE_TILE 128
#define N_CTILE   (KCB / CODE_TILE)   // 32
#define MAX_CAND  64

// ---------------- device scratch (no allocations allowed) -------------------
__device__ float  g_S[N_TOK];
__device__ float  g_c[KCB];
__device__ float  g_loss[N_TOK];
__device__ double g_part[128];
__device__ float  g_sx[N_TOK], g_Lx[N_TOK];
__device__ float  g_se[KCB],  g_Le[KCB];
__device__ float  g_maxse, g_maxLe;
__device__ __align__(16) int g_XqT[NKCH * N_TOK];   // [kchunk][token]  8MB
__device__ __align__(16) int g_EqT[NKCH * KCB];     // [kchunk][code]   1MB
__device__ unsigned short g_cand[N_TOK][MAX_CAND];
__device__ int    g_ncand[N_TOK];

// ---------------- helpers ----------------------------------------------------
__device__ __forceinline__ uint32_t smem_to_u32(const void* p) {
    uint32_t a;
    asm("{ .reg .u64 t; cvta.to.shared.u64 t, %1; cvt.u32.u64 %0, t; }" : "=r"(a) : "l"(p));
    return a;
}
__device__ __forceinline__ void dp4a(int& acc, int a, int b) {
    asm("dp4a.s32.s32 %0, %1, %2, %0;" : "+r"(acc) : "r"(a), "r"(b));
}
__device__ __forceinline__ void cp_async16(uint32_t dst_smem, const void* src) {
    asm volatile("cp.async.cg.shared.global [%0], [%1], 16;" :: "r"(dst_smem), "l"(src) : "memory");
}
__device__ __forceinline__ void cp_commit() { asm volatile("cp.async.commit_group;" ::: "memory"); }
__device__ __forceinline__ void cp_wait0()  { asm volatile("cp.async.wait_group 0;"  ::: "memory"); }

// order-preserving float<->uint encoding (positive-and-inf safe both ways)
__device__ __forceinline__ uint32_t fenc(float f) {
    uint32_t u = __float_as_uint(f);
    return (u & 0x80000000u) ? ~u : (u | 0x80000000u);
}
__device__ __forceinline__ float fdec(uint32_t u) {
    uint32_t b = (u & 0x80000000u) ? (u & 0x7FFFFFFFu) : ~u;
    return __uint_as_float(b);
}
__device__ __forceinline__ int q8(float v, float inv) {
    int q = __float2int_rn(v * inv);
    return max(-127, min(127, q));
}

// ---------------------------------------------------------------------------
// Kernel 1: per-row exact-fp32 sums of squares (bit-matching R2 chain),
// per-row max/L1, int8 quantization into TRANSPOSED packed layout.
// ---------------------------------------------------------------------------
__global__ void prep_kernel(const float* __restrict__ X, const float* __restrict__ E) {
    int i = blockIdx.x * blockDim.x + threadIdx.x;
    if (i < N_TOK) {
        g_ncand[i] = 0;
        const float4* row = reinterpret_cast<const float4*>(X + (size_t)i * DIM);
        float s = 0.0f, mx = 0.0f, l1 = 0.0f;
        #pragma unroll 8
        for (int j = 0; j < DIM / 4; j++) {
            float4 v = row[j];
            s = __fadd_rn(s, __fmul_rn(v.x, v.x));
            s = __fadd_rn(s, __fmul_rn(v.y, v.y));
            s = __fadd_rn(s, __fmul_rn(v.z, v.z));
            s = __fadd_rn(s, __fmul_rn(v.w, v.w));
            float ax = fabsf(v.x), ay = fabsf(v.y), az = fabsf(v.z), aw = fabsf(v.w);
            mx = fmaxf(fmaxf(mx, ax), fmaxf(ay, fmaxf(az, aw)));
            l1 += ax + ay + az + aw;
        }
        g_S[i] = s;
        mx = fmaxf(mx, 1e-30f);
        float inv = 127.0f / mx;
        g_sx[i] = mx / 127.0f;
        g_Lx[i] = l1;
        #pragma unroll 8
        for (int k = 0; k < NKCH; k++) {
            float4 v = row[k];
            int q0 = q8(v.x, inv), q1 = q8(v.y, inv), q2 = q8(v.z, inv), q3 = q8(v.w, inv);
            g_XqT[k * N_TOK + i] = (q0 & 255) | ((q1 & 255) << 8) | ((q2 & 255) << 16) | ((q3 & 255) << 24);
        }
    }
    if (i < KCB) {
        const float4* row = reinterpret_cast<const float4*>(E + (size_t)i * DIM);
        float s = 0.0f, mx = 0.0f, l1 = 0.0f;
        #pragma unroll 8
        for (int j = 0; j < DIM / 4; j++) {
            float4 v = row[j];
            s = __fadd_rn(s, __fmul_rn(v.x, v.x));
            s = __fadd_rn(s, __fmul_rn(v.y, v.y));
            s = __fadd_rn(s, __fmul_rn(v.z, v.z));
            s = __fadd_rn(s, __fmul_rn(v.w, v.w));
            float ax = fabsf(v.x), ay = fabsf(v.y), az = fabsf(v.z), aw = fabsf(v.w);
            mx = fmaxf(fmaxf(mx, ax), fmaxf(ay, fmaxf(az, aw)));
            l1 += ax + ay + az + aw;
        }
        g_c[i] = s;
        mx = fmaxf(mx, 1e-30f);
        float inv = 127.0f / mx;
        g_se[i] = mx / 127.0f;
        g_Le[i] = l1;
        #pragma unroll 8
        for (int k = 0; k < NKCH; k++) {
            float4 v = row[k];
            int q0 = q8(v.x, inv), q1 = q8(v.y, inv), q2 = q8(v.z, inv), q3 = q8(v.w, inv);
            g_EqT[k * KCB + i] = (q0 & 255) | ((q1 & 255) << 8) | ((q2 & 255) << 16) | ((q3 & 255) << 24);
        }
    }
}

// ---------------------------------------------------------------------------
// Kernel 2: global max of se / Le over codes (for rigorous per-token margins).
// ---------------------------------------------------------------------------
__global__ void reduce_kernel() {
    __shared__ float s1[256], s2[256];
    float m1 = 0.0f, m2 = 0.0f;
    for (int j = threadIdx.x; j < KCB; j += 256) {
        m1 = fmaxf(m1, g_se[j]);
        m2 = fmaxf(m2, g_Le[j]);
    }
    s1[threadIdx.x] = m1; s2[threadIdx.x] = m2;
    __syncthreads();
    for (int off = 128; off >= 1; off >>= 1) {
        if (threadIdx.x < off) {
            s1[threadIdx.x] = fmaxf(s1[threadIdx.x], s1[threadIdx.x + off]);
            s2[threadIdx.x] = fmaxf(s2[threadIdx.x], s2[threadIdx.x + off]);
        }
        __syncthreads();
    }
    if (threadIdx.x == 0) { g_maxse = s1[0]; g_maxLe = s2[0]; }
}

// ---------------------------------------------------------------------------
// Kernel 3: int8 dp4a coarse GEMM + margin candidate collection.
// CTA = 128 tokens x 4096 codes (32 tiles of 128). 256 threads as 16(ty)x16(tx),
// 8 tokens x 8 codes per thread, exact int32 dots. Coarse score
// s_hat = fmaf(-2*sx_i*se_j, (float)dot, c_j); per-token rigorous margin.
// smem ~98KB -> 2 CTAs/SM.
// ---------------------------------------------------------------------------
#define SM_X    0                     // int Xs[64][128]            32KB
#define SM_E    32768                 // int Es[2][64][128]         64KB
#define SM_MIN  98304                 // uint smin[128]
#define SM_MARG 98816                 // float marg[128]
#define SM_SX   99328                 // float sx[128]
#define SMEM_TOTAL 99840

__global__ __launch_bounds__(256) void coarse_kernel() {
    extern __shared__ __align__(16) char smem[];
    const int tid = threadIdx.x;
    const int tx = tid & 15, ty = tid >> 4;
    const int mb = blockIdx.x * TOK_TILE;
    uint32_t sb = smem_to_u32(smem);
    int* Xs = reinterpret_cast<int*>(smem + SM_X);
    int* Es = reinterpret_cast<int*>(smem + SM_E);
    uint32_t* smin = reinterpret_cast<uint32_t*>(smem + SM_MIN);
    float* marg_s = reinterpret_cast<float*>(smem + SM_MARG);
    float* sx_s = reinterpret_cast<float*>(smem + SM_SX);

    if (tid < TOK_TILE) {
        smin[tid] = 0xFF800000u;  // fenc(+inf)
        float sx = g_sx[mb + tid];
        float lx = g_Lx[mb + tid];
        float mse = g_maxse, mle = g_maxLe;
        sx_s[tid] = sx;
        // 2*(quant bound) + slop covering fp32 d2-chain rounding slack
        marg_s[tid] = 2.0f * (0.5f * sx * mle + 0.5f * mse * lx + 128.0f * sx * mse) + 3.0e-4f;
    }

    // X tile: 64 kchunks x 128 tokens (cp.async, contiguous 512B rows)
    #pragma unroll
    for (int k = 0; k < 8; k++) {
        int v = tid + k * 256;
        int row = v >> 5, ch = v & 31;
        cp_async16(sb + SM_X + (row * 128 + ch * 4) * 4,
                   g_XqT + (size_t)row * N_TOK + mb + ch * 4);
    }
    // E tile 0
    #pragma unroll
    for (int k = 0; k < 8; k++) {
        int v = tid + k * 256;
        int row = v >> 5, ch = v & 31;
        cp_async16(sb + SM_E + (row * 128 + ch * 4) * 4,
                   g_EqT + (size_t)row * KCB + ch * 4);
    }
    cp_commit();
    cp_wait0();
    __syncthreads();

    float sxv[8];
    #pragma unroll
    for (int i = 0; i < 8; i++) sxv[i] = sx_s[ty * 8 + i];

    for (int ct = 0; ct < N_CTILE; ct++) {
        const int cur = ct & 1;

        if (ct < N_CTILE - 1) {
            #pragma unroll
            for (int k = 0; k < 8; k++) {
                int v = tid + k * 256;
                int row = v >> 5, ch = v & 31;
                cp_async16(sb + SM_E + ((cur ^ 1) * 8192 + row * 128 + ch * 4) * 4,
                           g_EqT + (size_t)row * KCB + (ct + 1) * CODE_TILE + ch * 4);
            }
            cp_commit();
        }

        int acc[8][8];
        #pragma unroll
        for (int i = 0; i < 8; i++)
            #pragma unroll
            for (int j = 0; j < 8; j++) acc[i][j] = 0;

        const int* eb = Es + cur * 8192;
        #pragma unroll 4
        for (int kc = 0; kc < NKCH; kc++) {
            int4 a0 = *reinterpret_cast<const int4*>(Xs + kc * 128 + ty * 8);
            int4 a1 = *reinterpret_cast<const int4*>(Xs + kc * 128 + ty * 8 + 4);
            int4 b0 = *reinterpret_cast<const int4*>(eb + kc * 128 + tx * 8);
            int4 b1 = *reinterpret_cast<const int4*>(eb + kc * 128 + tx * 8 + 4);
            int aw[8] = {a0.x, a0.y, a0.z, a0.w, a1.x, a1.y, a1.z, a1.w};
            int bw[8] = {b0.x, b0.y, b0.z, b0.w, b1.x, b1.y, b1.z, b1.w};
            #pragma unroll
            for (int i = 0; i < 8; i++)
                #pragma unroll
                for (int j = 0; j < 8; j++)
                    dp4a(acc[i][j], aw[i], bw[j]);
        }

        // epilogue
        float se8[8], c8[8];
        #pragma unroll
        for (int j = 0; j < 8; j++) {
            int code = ct * CODE_TILE + tx * 8 + j;
            se8[j] = __ldg(&g_se[code]);
            c8[j]  = __ldg(&g_c[code]);
        }
        #pragma unroll
        for (int i = 0; i < 8; i++) {
            const int tl = ty * 8 + i;
            const float nsx = -2.0f * sxv[i];
            float s[8];
            float tmin = CUDART_INF_F;
            #pragma unroll
            for (int j = 0; j < 8; j++) {
                s[j] = fmaf(nsx * se8[j], (float)acc[i][j], c8[j]);
                tmin = fminf(tmin, s[j]);
            }
            float curf = fdec(smin[tl]);      // stale-larger read is safe
            if (tmin < curf) atomicMin(&smin[tl], fenc(tmin));
            const float th = fminf(curf, tmin) + marg_s[tl];
            if (tmin <= th) {
                #pragma unroll
                for (int j = 0; j < 8; j++) {
                    if (s[j] <= th) {
                        int code = ct * CODE_TILE + tx * 8 + j;
                        int p = atomicAdd(&g_ncand[mb + tl], 1);
                        if (p < MAX_CAND) g_cand[mb + tl][p] = (unsigned short)code;
                    }
                }
            }
        }

        if (ct < N_CTILE - 1) cp_wait0();
        __syncthreads();
    }
}

// ---------------------------------------------------------------------------
// Kernel 4: exact fp32 rescore (bit-identical R2 chain) + gather + STE output
// + per-token loss, merged. One warp per token.
// ---------------------------------------------------------------------------
__global__ void rescore_output_kernel(const float* __restrict__ X, const float* __restrict__ E,
                                      float* __restrict__ out_q, float* __restrict__ out_idx_f) {
    int token = (blockIdx.x * blockDim.x + threadIdx.x) >> 5;
    int lane = threadIdx.x & 31;
    if (token >= N_TOK) return;
    int n = g_ncand[token];
    float S = g_S[token];
    const float4* xr = reinterpret_cast<const float4*>(X + (size_t)token * DIM);

    float bestv = CUDART_INF_F;
    int   besti = 0x7fffffff;

    if (n <= MAX_CAND) {
        for (int sidx = lane; sidx < n; sidx += 32) {
            int code = g_cand[token][sidx];
            const float4* er = reinterpret_cast<const float4*>(E + (size_t)code * DIM);
            float m = 0.0f;
            #pragma unroll 8
            for (int k = 0; k < DIM / 4; k++) {
                float4 x = xr[k], e = er[k];
                m = fmaf(x.x, e.x, m); m = fmaf(x.y, e.y, m);
                m = fmaf(x.z, e.z, m); m = fmaf(x.w, e.w, m);
            }
            float t = fmaf(-2.0f, m, S);
            float d2 = __fadd_rn(t, g_c[code]);
            if (d2 < bestv || (d2 == bestv && code < besti)) { bestv = d2; besti = code; }
        }
    } else {
        for (int code = lane; code < KCB; code += 32) {
            const float4* er = reinterpret_cast<const float4*>(E + (size_t)code * DIM);
            float m = 0.0f;
            #pragma unroll 8
            for (int k = 0; k < DIM / 4; k++) {
                float4 x = xr[k], e = er[k];
                m = fmaf(x.x, e.x, m); m = fmaf(x.y, e.y, m);
                m = fmaf(x.z, e.z, m); m = fmaf(x.w, e.w, m);
            }
            float t = fmaf(-2.0f, m, S);
            float d2 = __fadd_rn(t, g_c[code]);
            if (d2 < bestv || (d2 == bestv && code < besti)) { bestv = d2; besti = code; }
        }
    }
    #pragma unroll
    for (int off = 16; off >= 1; off >>= 1) {
        float ov = __shfl_xor_sync(0xffffffffu, bestv, off);
        int   oi = __shfl_xor_sync(0xffffffffu, besti, off);
        if (ov < bestv || (ov == bestv && oi < besti)) { bestv = ov; besti = oi; }
    }
    besti = __shfl_sync(0xffffffffu, besti, 0);

    // gather + straight-through + loss (bit-exact R2 arithmetic)
    const float4* er = reinterpret_cast<const float4*>(E + (size_t)besti * DIM);
    float* qr = out_q + (size_t)token * DIM;   // 4B-aligned only -> scalar stores
    float ls = 0.0f;
    #pragma unroll
    for (int j = lane; j < DIM / 4; j += 32) {
        float4 x = xr[j], e = er[j];
        float4 d, o;
        d.x = __fadd_rn(e.x, -x.x); d.y = __fadd_rn(e.y, -x.y);
        d.z = __fadd_rn(e.z, -x.z); d.w = __fadd_rn(e.w, -x.w);
        ls = __fadd_rn(ls, __fmul_rn(d.x, d.x));
        ls = __fadd_rn(ls, __fmul_rn(d.y, d.y));
        ls = __fadd_rn(ls, __fmul_rn(d.z, d.z));
        ls = __fadd_rn(ls, __fmul_rn(d.w, d.w));
        o.x = __fadd_rn(x.x, d.x); o.y = __fadd_rn(x.y, d.y);
        o.z = __fadd_rn(x.z, d.z); o.w = __fadd_rn(x.w, d.w);
        qr[j * 4 + 0] = o.x;
        qr[j * 4 + 1] = o.y;
        qr[j * 4 + 2] = o.z;
        qr[j * 4 + 3] = o.w;
    }
    #pragma unroll
    for (int off = 16; off >= 1; off >>= 1)
        ls = __fadd_rn(ls, __shfl_xor_sync(0xffffffffu, ls, off));
    if (lane == 0) {
        g_loss[token] = ls;
        out_idx_f[token] = (float)besti;
    }
}

// ---------------------------------------------------------------------------
// Kernels 5+6: two-stage deterministic double-precision loss reduction.
// ---------------------------------------------------------------------------
__global__ void finalize1_kernel() {
    __shared__ double sh[256];
    int b = blockIdx.x;
    sh[threadIdx.x] = (double)g_loss[b * 256 + threadIdx.x];
    __syncthreads();
    for (int off = 128; off >= 1; off >>= 1) {
        if (threadIdx.x < off) sh[threadIdx.x] += sh[threadIdx.x + off];
        __syncthreads();
    }
    if (threadIdx.x == 0) g_part[b] = sh[0];
}
__global__ void finalize2_kernel(float* __restrict__ out) {
    __shared__ double sh[128];
    sh[threadIdx.x] = g_part[threadIdx.x];
    __syncthreads();
    for (int off = 64; off >= 1; off >>= 1) {
        if (threadIdx.x < off) sh[threadIdx.x] += sh[threadIdx.x + off];
        __syncthreads();
    }
    if (threadIdx.x == 0)
        out[0] = (float)(0.5 * sh[0] / ((double)N_TOK * (double)DIM));
}

// ---------------------------------------------------------------------------
extern "C" void kernel_launch(void* const* d_in, const int* in_sizes, int n_in,
                              void* d_out, int out_size) {
    const float* X = (const float*)d_in[0];   // embedding_tokens [N, D]
    const float* E = (const float*)d_in[1];   // embeddings       [K, D]
    float* out = (float*)d_out;
    float* out_q   = out + 1;
    float* out_idx = out + 1 + (size_t)N_TOK * DIM;

    static int smem_set = 0;
    if (!smem_set) {
        cudaFuncSetAttribute(coarse_kernel, cudaFuncAttributeMaxDynamicSharedMemorySize, SMEM_TOTAL);
        smem_set = 1;
    }

    prep_kernel<<<N_TOK / 256, 256>>>(X, E);
    reduce_kernel<<<1, 256>>>();
    coarse_kernel<<<N_TOK / TOK_TILE, 256, SMEM_TOTAL>>>();
    rescore_output_kernel<<<(N_TOK * 32) / 256, 256>>>(X, E, out_q, out_idx);
    finalize1_kernel<<<128, 256>>>();
    finalize2_kernel<<<1, 128>>>(out);
}

// round 8
// speedup vs baseline: 25.7848x; 1.2559x over previous
#include <cuda_runtime.h>
#include <math_constants.h>
#include <cstdint>

// Problem constants: B=16,T=2048,D=256,K=4096
#define N_TOK 32768
#define DIM   256
#define KCB   4096
#define NKCH  (DIM / 4)     // 64 packed int32 k-chunks per row

#define TOK_TILE  128
#define CODE_TILE 128
#define N_CTILE   (KCB / CODE_TILE)   // 32
#define MAX_CAND  64

// ---------------- device scratch (no allocations allowed) -------------------
__device__ float  g_S[N_TOK];
__device__ float  g_c[KCB];
__device__ float  g_loss[N_TOK];
__device__ double g_part[128];
__device__ float  g_sx[N_TOK], g_Lx[N_TOK];
__device__ float  g_se[KCB],  g_Le[KCB];
__device__ float  g_maxse, g_maxLe;
__device__ __align__(16) int g_XqT[NKCH * N_TOK];   // [kchunk][token]  8MB
__device__ __align__(16) int g_EqT[NKCH * KCB];     // [kchunk][code]   1MB
__device__ unsigned short g_cand[N_TOK][MAX_CAND];
__device__ int    g_ncand[N_TOK];

// ---------------- helpers ----------------------------------------------------
__device__ __forceinline__ uint32_t smem_to_u32(const void* p) {
    uint32_t a;
    asm("{ .reg .u64 t; cvta.to.shared.u64 t, %1; cvt.u32.u64 %0, t; }" : "=r"(a) : "l"(p));
    return a;
}
__device__ __forceinline__ void dp4a(int& acc, int a, int b) {
    asm("dp4a.s32.s32 %0, %1, %2, %0;" : "+r"(acc) : "r"(a), "r"(b));
}
__device__ __forceinline__ void cp_async16(uint32_t dst_smem, const void* src) {
    asm volatile("cp.async.cg.shared.global [%0], [%1], 16;" :: "r"(dst_smem), "l"(src) : "memory");
}
__device__ __forceinline__ void cp_commit() { asm volatile("cp.async.commit_group;" ::: "memory"); }
__device__ __forceinline__ void cp_wait0()  { asm volatile("cp.async.wait_group 0;"  ::: "memory"); }
__device__ __forceinline__ int q8(float v, float inv) {
    int q = __float2int_rn(v * inv);
    return max(-127, min(127, q));
}

// ---------------------------------------------------------------------------
// Kernel 1: per-row exact-fp32 sums of squares (bit-matching R2 chain),
// per-row max/L1, int8 quantization into TRANSPOSED packed layout.
// ---------------------------------------------------------------------------
__global__ void prep_kernel(const float* __restrict__ X, const float* __restrict__ E) {
    int i = blockIdx.x * blockDim.x + threadIdx.x;
    if (i < N_TOK) {
        g_ncand[i] = 0;
        const float4* row = reinterpret_cast<const float4*>(X + (size_t)i * DIM);
        float s = 0.0f, mx = 0.0f, l1 = 0.0f;
        #pragma unroll 8
        for (int j = 0; j < DIM / 4; j++) {
            float4 v = row[j];
            s = __fadd_rn(s, __fmul_rn(v.x, v.x));
            s = __fadd_rn(s, __fmul_rn(v.y, v.y));
            s = __fadd_rn(s, __fmul_rn(v.z, v.z));
            s = __fadd_rn(s, __fmul_rn(v.w, v.w));
            float ax = fabsf(v.x), ay = fabsf(v.y), az = fabsf(v.z), aw = fabsf(v.w);
            mx = fmaxf(fmaxf(mx, ax), fmaxf(ay, fmaxf(az, aw)));
            l1 += ax + ay + az + aw;
        }
        g_S[i] = s;
        mx = fmaxf(mx, 1e-30f);
        float inv = 127.0f / mx;
        g_sx[i] = mx / 127.0f;
        g_Lx[i] = l1;
        #pragma unroll 8
        for (int k = 0; k < NKCH; k++) {
            float4 v = row[k];
            int q0 = q8(v.x, inv), q1 = q8(v.y, inv), q2 = q8(v.z, inv), q3 = q8(v.w, inv);
            g_XqT[k * N_TOK + i] = (q0 & 255) | ((q1 & 255) << 8) | ((q2 & 255) << 16) | ((q3 & 255) << 24);
        }
    }
    if (i < KCB) {
        const float4* row = reinterpret_cast<const float4*>(E + (size_t)i * DIM);
        float s = 0.0f, mx = 0.0f, l1 = 0.0f;
        #pragma unroll 8
        for (int j = 0; j < DIM / 4; j++) {
            float4 v = row[j];
            s = __fadd_rn(s, __fmul_rn(v.x, v.x));
            s = __fadd_rn(s, __fmul_rn(v.y, v.y));
            s = __fadd_rn(s, __fmul_rn(v.z, v.z));
            s = __fadd_rn(s, __fmul_rn(v.w, v.w));
            float ax = fabsf(v.x), ay = fabsf(v.y), az = fabsf(v.z), aw = fabsf(v.w);
            mx = fmaxf(fmaxf(mx, ax), fmaxf(ay, fmaxf(az, aw)));
            l1 += ax + ay + az + aw;
        }
        g_c[i] = s;
        mx = fmaxf(mx, 1e-30f);
        float inv = 127.0f / mx;
        g_se[i] = mx / 127.0f;
        g_Le[i] = l1;
        #pragma unroll 8
        for (int k = 0; k < NKCH; k++) {
            float4 v = row[k];
            int q0 = q8(v.x, inv), q1 = q8(v.y, inv), q2 = q8(v.z, inv), q3 = q8(v.w, inv);
            g_EqT[k * KCB + i] = (q0 & 255) | ((q1 & 255) << 8) | ((q2 & 255) << 16) | ((q3 & 255) << 24);
        }
    }
}

// ---------------------------------------------------------------------------
// Kernel 2: global max of se / Le over codes (for rigorous per-token margins).
// ---------------------------------------------------------------------------
__global__ void reduce_kernel() {
    __shared__ float s1[256], s2[256];
    float m1 = 0.0f, m2 = 0.0f;
    for (int j = threadIdx.x; j < KCB; j += 256) {
        m1 = fmaxf(m1, g_se[j]);
        m2 = fmaxf(m2, g_Le[j]);
    }
    s1[threadIdx.x] = m1; s2[threadIdx.x] = m2;
    __syncthreads();
    for (int off = 128; off >= 1; off >>= 1) {
        if (threadIdx.x < off) {
            s1[threadIdx.x] = fmaxf(s1[threadIdx.x], s1[threadIdx.x + off]);
            s2[threadIdx.x] = fmaxf(s2[threadIdx.x], s2[threadIdx.x + off]);
        }
        __syncthreads();
    }
    if (threadIdx.x == 0) { g_maxse = s1[0]; g_maxLe = s2[0]; }
}

// ---------------------------------------------------------------------------
// Kernel 3: int8 dp4a coarse GEMM + margin candidate collection.
// CTA = 128 tokens x 4096 codes (32 tiles of 128). 256 threads as 16(ty)x16(tx),
// 8 tokens x 8 codes per thread, exact int32 dots.
// For each token, its 16 code-lanes form one half-warp: the tile-wide min is
// computed by a 4-step shfl_xor reduction, and the token's running min lives
// in a register. Collection threshold = runmin + per-token rigorous margin
// => candidate set provably contains the exact fp32 argmin, count ~6-10.
// ---------------------------------------------------------------------------
#define SM_X    0                     // int Xs[64][128]            32KB
#define SM_E    32768                 // int Es[2][64][128]         64KB
#define SM_MARG 98304                 // float marg[128]
#define SM_SX   98816                 // float sx[128]
#define SMEM_TOTAL 99328

__global__ __launch_bounds__(256) void coarse_kernel() {
    extern __shared__ __align__(16) char smem[];
    const int tid = threadIdx.x;
    const int tx = tid & 15, ty = tid >> 4;
    const int mb = blockIdx.x * TOK_TILE;
    uint32_t sb = smem_to_u32(smem);
    int* Xs = reinterpret_cast<int*>(smem + SM_X);
    int* Es = reinterpret_cast<int*>(smem + SM_E);
    float* marg_s = reinterpret_cast<float*>(smem + SM_MARG);
    float* sx_s = reinterpret_cast<float*>(smem + SM_SX);

    if (tid < TOK_TILE) {
        float sx = g_sx[mb + tid];
        float lx = g_Lx[mb + tid];
        float mse = g_maxse, mle = g_maxLe;
        sx_s[tid] = sx;
        // 2*(quant bound) + slop covering fp32 d2-chain rounding slack
        marg_s[tid] = 2.0f * (0.5f * sx * mle + 0.5f * mse * lx + 128.0f * sx * mse) + 3.0e-4f;
    }

    // X tile: 64 kchunks x 128 tokens (cp.async, contiguous 512B rows)
    #pragma unroll
    for (int k = 0; k < 8; k++) {
        int v = tid + k * 256;
        int row = v >> 5, ch = v & 31;
        cp_async16(sb + SM_X + (row * 128 + ch * 4) * 4,
                   g_XqT + (size_t)row * N_TOK + mb + ch * 4);
    }
    // E tile 0
    #pragma unroll
    for (int k = 0; k < 8; k++) {
        int v = tid + k * 256;
        int row = v >> 5, ch = v & 31;
        cp_async16(sb + SM_E + (row * 128 + ch * 4) * 4,
                   g_EqT + (size_t)row * KCB + ch * 4);
    }
    cp_commit();
    cp_wait0();
    __syncthreads();

    float sxv[8], margv[8], runmin[8];
    #pragma unroll
    for (int i = 0; i < 8; i++) {
        sxv[i]   = sx_s[ty * 8 + i];
        margv[i] = marg_s[ty * 8 + i];
        runmin[i] = CUDART_INF_F;
    }

    for (int ct = 0; ct < N_CTILE; ct++) {
        const int cur = ct & 1;

        if (ct < N_CTILE - 1) {
            #pragma unroll
            for (int k = 0; k < 8; k++) {
                int v = tid + k * 256;
                int row = v >> 5, ch = v & 31;
                cp_async16(sb + SM_E + ((cur ^ 1) * 8192 + row * 128 + ch * 4) * 4,
                           g_EqT + (size_t)row * KCB + (ct + 1) * CODE_TILE + ch * 4);
            }
            cp_commit();
        }

        int acc[8][8];
        #pragma unroll
        for (int i = 0; i < 8; i++)
            #pragma unroll
            for (int j = 0; j < 8; j++) acc[i][j] = 0;

        const int* eb = Es + cur * 8192;
        #pragma unroll 4
        for (int kc = 0; kc < NKCH; kc++) {
            int4 a0 = *reinterpret_cast<const int4*>(Xs + kc * 128 + ty * 8);
            int4 a1 = *reinterpret_cast<const int4*>(Xs + kc * 128 + ty * 8 + 4);
            int4 b0 = *reinterpret_cast<const int4*>(eb + kc * 128 + tx * 8);
            int4 b1 = *reinterpret_cast<const int4*>(eb + kc * 128 + tx * 8 + 4);
            int aw[8] = {a0.x, a0.y, a0.z, a0.w, a1.x, a1.y, a1.z, a1.w};
            int bw[8] = {b0.x, b0.y, b0.z, b0.w, b1.x, b1.y, b1.z, b1.w};
            #pragma unroll
            for (int i = 0; i < 8; i++)
                #pragma unroll
                for (int j = 0; j < 8; j++)
                    dp4a(acc[i][j], aw[i], bw[j]);
        }

        // epilogue: s_hat, half-warp tile-min reduce, running-min collection
        float se8[8], c8[8];
        #pragma unroll
        for (int j = 0; j < 8; j++) {
            int code = ct * CODE_TILE + tx * 8 + j;
            se8[j] = __ldg(&g_se[code]);
            c8[j]  = __ldg(&g_c[code]);
        }
        #pragma unroll
        for (int i = 0; i < 8; i++) {
            const float nsx = -2.0f * sxv[i];
            float s[8];
            float tmin = CUDART_INF_F;
            #pragma unroll
            for (int j = 0; j < 8; j++) {
                s[j] = fmaf(nsx * se8[j], (float)acc[i][j], c8[j]);
                tmin = fminf(tmin, s[j]);
            }
            // reduce tile-min across the 16 code-lanes (same half-warp)
            #pragma unroll
            for (int off = 8; off >= 1; off >>= 1)
                tmin = fminf(tmin, __shfl_xor_sync(0xffffffffu, tmin, off));
            runmin[i] = fminf(runmin[i], tmin);
            const float th = runmin[i] + margv[i];
            bool any = false;
            #pragma unroll
            for (int j = 0; j < 8; j++) any |= (s[j] <= th);
            if (any) {
                const int token = mb + ty * 8 + i;
                #pragma unroll
                for (int j = 0; j < 8; j++) {
                    if (s[j] <= th) {
                        int code = ct * CODE_TILE + tx * 8 + j;
                        int p = atomicAdd(&g_ncand[token], 1);
                        if (p < MAX_CAND) g_cand[token][p] = (unsigned short)code;
                    }
                }
            }
        }

        if (ct < N_CTILE - 1) cp_wait0();
        __syncthreads();
    }
}

// ---------------------------------------------------------------------------
// Kernel 4: exact fp32 rescore (bit-identical R2 chain) + gather + STE output
// + per-token loss, merged. One warp per token.
// ---------------------------------------------------------------------------
__global__ void rescore_output_kernel(const float* __restrict__ X, const float* __restrict__ E,
                                      float* __restrict__ out_q, float* __restrict__ out_idx_f) {
    int token = (blockIdx.x * blockDim.x + threadIdx.x) >> 5;
    int lane = threadIdx.x & 31;
    if (token >= N_TOK) return;
    int n = g_ncand[token];
    float S = g_S[token];
    const float4* xr = reinterpret_cast<const float4*>(X + (size_t)token * DIM);

    float bestv = CUDART_INF_F;
    int   besti = 0x7fffffff;

    if (n <= MAX_CAND) {
        for (int sidx = lane; sidx < n; sidx += 32) {
            int code = g_cand[token][sidx];
            const float4* er = reinterpret_cast<const float4*>(E + (size_t)code * DIM);
            float m = 0.0f;
            #pragma unroll 8
            for (int k = 0; k < DIM / 4; k++) {
                float4 x = xr[k], e = er[k];
                m = fmaf(x.x, e.x, m); m = fmaf(x.y, e.y, m);
                m = fmaf(x.z, e.z, m); m = fmaf(x.w, e.w, m);
            }
            float t = fmaf(-2.0f, m, S);
            float d2 = __fadd_rn(t, g_c[code]);
            if (d2 < bestv || (d2 == bestv && code < besti)) { bestv = d2; besti = code; }
        }
    } else {
        for (int code = lane; code < KCB; code += 32) {
            const float4* er = reinterpret_cast<const float4*>(E + (size_t)code * DIM);
            float m = 0.0f;
            #pragma unroll 8
            for (int k = 0; k < DIM / 4; k++) {
                float4 x = xr[k], e = er[k];
                m = fmaf(x.x, e.x, m); m = fmaf(x.y, e.y, m);
                m = fmaf(x.z, e.z, m); m = fmaf(x.w, e.w, m);
            }
            float t = fmaf(-2.0f, m, S);
            float d2 = __fadd_rn(t, g_c[code]);
            if (d2 < bestv || (d2 == bestv && code < besti)) { bestv = d2; besti = code; }
        }
    }
    #pragma unroll
    for (int off = 16; off >= 1; off >>= 1) {
        float ov = __shfl_xor_sync(0xffffffffu, bestv, off);
        int   oi = __shfl_xor_sync(0xffffffffu, besti, off);
        if (ov < bestv || (ov == bestv && oi < besti)) { bestv = ov; besti = oi; }
    }
    besti = __shfl_sync(0xffffffffu, besti, 0);

    // gather + straight-through + loss (bit-exact R2 arithmetic)
    const float4* er = reinterpret_cast<const float4*>(E + (size_t)besti * DIM);
    float* qr = out_q + (size_t)token * DIM;   // 4B-aligned only -> scalar stores
    float ls = 0.0f;
    #pragma unroll
    for (int j = lane; j < DIM / 4; j += 32) {
        float4 x = xr[j], e = er[j];
        float4 d, o;
        d.x = __fadd_rn(e.x, -x.x); d.y = __fadd_rn(e.y, -x.y);
        d.z = __fadd_rn(e.z, -x.z); d.w = __fadd_rn(e.w, -x.w);
        ls = __fadd_rn(ls, __fmul_rn(d.x, d.x));
        ls = __fadd_rn(ls, __fmul_rn(d.y, d.y));
        ls = __fadd_rn(ls, __fmul_rn(d.z, d.z));
        ls = __fadd_rn(ls, __fmul_rn(d.w, d.w));
        o.x = __fadd_rn(x.x, d.x); o.y = __fadd_rn(x.y, d.y);
        o.z = __fadd_rn(x.z, d.z); o.w = __fadd_rn(x.w, d.w);
        qr[j * 4 + 0] = o.x;
        qr[j * 4 + 1] = o.y;
        qr[j * 4 + 2] = o.z;
        qr[j * 4 + 3] = o.w;
    }
    #pragma unroll
    for (int off = 16; off >= 1; off >>= 1)
        ls = __fadd_rn(ls, __shfl_xor_sync(0xffffffffu, ls, off));
    if (lane == 0) {
        g_loss[token] = ls;
        out_idx_f[token] = (float)besti;
    }
}

// ---------------------------------------------------------------------------
// Kernels 5+6: two-stage deterministic double-precision loss reduction.
// ---------------------------------------------------------------------------
__global__ void finalize1_kernel() {
    __shared__ double sh[256];
    int b = blockIdx.x;
    sh[threadIdx.x] = (double)g_loss[b * 256 + threadIdx.x];
    __syncthreads();
    for (int off = 128; off >= 1; off >>= 1) {
        if (threadIdx.x < off) sh[threadIdx.x] += sh[threadIdx.x + off];
        __syncthreads();
    }
    if (threadIdx.x == 0) g_part[b] = sh[0];
}
__global__ void finalize2_kernel(float* __restrict__ out) {
    __shared__ double sh[128];
    sh[threadIdx.x] = g_part[threadIdx.x];
    __syncthreads();
    for (int off = 64; off >= 1; off >>= 1) {
        if (threadIdx.x < off) sh[threadIdx.x] += sh[threadIdx.x + off];
        __syncthreads();
    }
    if (threadIdx.x == 0)
        out[0] = (float)(0.5 * sh[0] / ((double)N_TOK * (double)DIM));
}

// ---------------------------------------------------------------------------
extern "C" void kernel_launch(void* const* d_in, const int* in_sizes, int n_in,
                              void* d_out, int out_size) {
    const float* X = (const float*)d_in[0];   // embedding_tokens [N, D]
    const float* E = (const float*)d_in[1];   // embeddings       [K, D]
    float* out = (float*)d_out;
    float* out_q   = out + 1;
    float* out_idx = out + 1 + (size_t)N_TOK * DIM;

    static int smem_set = 0;
    if (!smem_set) {
        cudaFuncSetAttribute(coarse_kernel, cudaFuncAttributeMaxDynamicSharedMemorySize, SMEM_TOTAL);
        smem_set = 1;
    }

    prep_kernel<<<N_TOK / 256, 256>>>(X, E);
    reduce_kernel<<<1, 256>>>();
    coarse_kernel<<<N_TOK / TOK_TILE, 256, SMEM_TOTAL>>>();
    rescore_output_kernel<<<(N_TOK * 32) / 256, 256>>>(X, E, out_q, out_idx);
    finalize1_kernel<<<128, 256>>>();
    finalize2_kernel<<<1, 128>>>(out);
}